// round 13
// baseline (speedup 1.0000x reference)
#include <cuda_runtime.h>
#include <cstdint>
#include <cstddef>

#define BATCH  8
#define HIDC   128
#define HROWS  64
#define WCOLS  64
#define TSTEPS 127   // 2*W - 1

typedef unsigned long long ull;

// ---------------- scratch (static device globals; no runtime allocation) ----
__device__ float g_Z[(size_t)BATCH * HROWS * WCOLS * 512]; // [b][r][w][o], includes b_is
__device__ float g_h[2 * BATCH * (HROWS + 1) * HIDC];      // [parity][b][row+1][c]; slot 0 = zero pad
__device__ int   g_done[BATCH * 4 * 8];                    // per-(b,rg) counters, stride 8 ints

// ---------------- packed f32x2 helpers -------------------------------------
__device__ __forceinline__ ull fma2(ull a, ull b, ull c) {
    ull d;
    asm("fma.rn.f32x2 %0, %1, %2, %3;" : "=l"(d) : "l"(a), "l"(b), "l"(c));
    return d;
}
__device__ __forceinline__ ull dup2(float x) {
    ull d;
    asm("mov.b64 %0, {%1, %1};" : "=l"(d) : "f"(x));
    return d;
}
__device__ __forceinline__ float sigmoidf_fast(float z) {
    return __fdividef(1.0f, 1.0f + __expf(-z));
}
__device__ __forceinline__ float tanhf_fast(float z) {
    return 1.0f - __fdividef(2.0f, __expf(2.0f * z) + 1.0f);
}
__device__ __forceinline__ int ld_acquire_gpu(const int* p) {
    int v;
    asm volatile("ld.acquire.gpu.global.s32 %0, [%1];" : "=r"(v) : "l"(p) : "memory");
    return v;
}
__device__ __forceinline__ void red_release_add(int* p, int v) {
    asm volatile("red.release.gpu.global.add.s32 [%0], %1;" :: "l"(p), "r"(v) : "memory");
}

// ============================================================================
// Kernel 0: zero h state + flags (re-run on every graph replay)
// ============================================================================
__global__ void init_kernel() {
    int i = blockIdx.x * blockDim.x + threadIdx.x;
    const int n = 2 * BATCH * (HROWS + 1) * HIDC;
    if (i < n) g_h[i] = 0.0f;
    if (i < BATCH * 4 * 8) g_done[i] = 0;
}

// ============================================================================
// Kernel 1: Z[b][r][w][o] = b_is[o] + sum_c x[b][c][r][w] * w_is[o][c]
// grid = (512 = b*64+r, 4 out-tiles of 128), 256 threads
// ============================================================================
#define ZPREP_SMEM ((8192 + 128 * 132) * 4)

__global__ void __launch_bounds__(256) zprep_kernel(
    const float* __restrict__ x, const float* __restrict__ w_is,
    const float* __restrict__ b_is)
{
    extern __shared__ float sm1[];
    float* xsh = sm1;          // [k=128][w=64]
    float* wsh = sm1 + 8192;   // [k=128][ol=128 pad 132]

    const int tid = threadIdx.x;
    const int b   = blockIdx.x >> 6;
    const int r   = blockIdx.x & 63;
    const int nt  = blockIdx.y;

#pragma unroll 8
    for (int i = 0; i < 32; ++i) {
        int idx = tid + (i << 8);
        int c = idx >> 6, w = idx & 63;
        xsh[idx] = x[(((size_t)(b << 7) + c) << 12) + (r << 6) + w];
    }
#pragma unroll 8
    for (int i = 0; i < 64; ++i) {
        int idx = tid + (i << 8);
        int ol = idx >> 7, c = idx & 127;
        wsh[c * 132 + ol] = w_is[(((nt << 7) + ol) << 7) + c];
    }
    __syncthreads();

    const int pc = (tid & 15) << 2;  // 4 w-positions
    const int oc = (tid >> 4) << 3;  // 8 outputs
    ull acc[16];
#pragma unroll
    for (int i = 0; i < 16; ++i) acc[i] = 0ull;

#pragma unroll 4
    for (int k = 0; k < 128; ++k) {
        float4 xv = *(const float4*)(xsh + (k << 6) + pc);
        ulonglong2 w0 = *(const ulonglong2*)(wsh + k * 132 + oc);
        ulonglong2 w1 = *(const ulonglong2*)(wsh + k * 132 + oc + 4);
        ull x0 = dup2(xv.x), x1 = dup2(xv.y), x2 = dup2(xv.z), x3 = dup2(xv.w);
        acc[ 0] = fma2(x0, w0.x, acc[ 0]);  acc[ 1] = fma2(x0, w0.y, acc[ 1]);
        acc[ 2] = fma2(x0, w1.x, acc[ 2]);  acc[ 3] = fma2(x0, w1.y, acc[ 3]);
        acc[ 4] = fma2(x1, w0.x, acc[ 4]);  acc[ 5] = fma2(x1, w0.y, acc[ 5]);
        acc[ 6] = fma2(x1, w1.x, acc[ 6]);  acc[ 7] = fma2(x1, w1.y, acc[ 7]);
        acc[ 8] = fma2(x2, w0.x, acc[ 8]);  acc[ 9] = fma2(x2, w0.y, acc[ 9]);
        acc[10] = fma2(x2, w1.x, acc[10]);  acc[11] = fma2(x2, w1.y, acc[11]);
        acc[12] = fma2(x3, w0.x, acc[12]);  acc[13] = fma2(x3, w0.y, acc[13]);
        acc[14] = fma2(x3, w1.x, acc[14]);  acc[15] = fma2(x3, w1.y, acc[15]);
    }

    float bo[8];
#pragma unroll
    for (int j = 0; j < 8; ++j) bo[j] = b_is[(nt << 7) + oc + j];

#pragma unroll
    for (int p = 0; p < 4; ++p) {
        float2 a0 = *(float2*)&acc[p * 4 + 0];
        float2 a1 = *(float2*)&acc[p * 4 + 1];
        float2 a2 = *(float2*)&acc[p * 4 + 2];
        float2 a3 = *(float2*)&acc[p * 4 + 3];
        float* zp = g_Z + (((size_t)blockIdx.x << 6) + pc + p) * 512 + (nt << 7) + oc;
        *(float4*)(zp)     = make_float4(a0.x + bo[0], a0.y + bo[1], a1.x + bo[2], a1.y + bo[3]);
        *(float4*)(zp + 4) = make_float4(a2.x + bo[4], a2.y + bo[5], a3.x + bo[6], a3.y + bo[7]);
    }
}

// ============================================================================
// Kernel 2: persistent diagonal scan, 256 threads.
// grid = 128 CTAs: bx = b*16 + rg*4 + cg. CTA owns rows [rg*16, rg*16+16),
// hidden channels [cg*32, cg*32+32) -> gate outputs {g*128 + cg*32 + j}.
// Sync: per-(b,rg) release counters; wait own-rg and rg-1 counters >= 4t.
// ============================================================================
// Wsh [256][128] floats = 131072 B
// hsh float2 [m=16][k=256 pad 258]  = 33024 B  (h duplicated as (h,h))
// zsh [m=16][ol=128 pad 132] floats = 8448 B
#define SCAN_SMEM (131072 + 33024 + 8448)

__global__ void __launch_bounds__(256, 1) scan_kernel(
    const float* __restrict__ w_ss, const float* __restrict__ b_is,
    const float* __restrict__ b_ss, float* __restrict__ out)
{
    extern __shared__ float sm[];
    float*  Wsh = sm;                         // [k=256][ol=128]
    float2* hsh = (float2*)(sm + 32768);      // [m=16][k=256 pad 258]
    float*  zsh = sm + 32768 + 8256;          // [m=16][ol=128 pad 132]

    const int tid = threadIdx.x;
    const int bx  = blockIdx.x;
    const int cg  = bx & 3;
    const int rg  = (bx >> 2) & 3;
    const int b   = bx >> 4;
    const int r0  = rg << 4;
    const int cbase = cg << 5;

    // resident weights: k<128 -> (dk=0, c=k) pairs h[r-1]; k>=128 -> (dk=1, c=k-128) pairs h[r]
#pragma unroll 4
    for (int i = 0; i < 128; ++i) {
        int idx = tid + (i << 8);
        int k = idx >> 7, ol = idx & 127;
        int g = ol >> 5, j = ol & 31;
        int oglb = (g << 7) + cbase + j;
        int dk = k >> 7, c = k & 127;
        Wsh[idx] = w_ss[(oglb << 8) + (c << 1) + dk];
    }

    // update-phase mapping: row mu (16), 2 channels jq, jq+1 within cg
    const int mu = tid >> 4;
    const int jq = (tid & 15) << 1;
    const int ru = r0 + mu;

    float bisr[8], bssr[8];
#pragma unroll
    for (int g = 0; g < 4; ++g)
#pragma unroll
        for (int q = 0; q < 2; ++q) {
            int o = (g << 7) + cbase + jq + q;
            bisr[g * 2 + q] = b_is[o];
            bssr[g * 2 + q] = b_ss[o];
        }
    float creg[2] = {0.f, 0.f};

    // GEMM mapping: warp tr handles rows 2tr, 2tr+1; lane tc handles outs 4tc..4tc+3
    const int tc = tid & 31;
    const int tr = tid >> 5;
    const float*  wcol = Wsh + (tc << 2);
    const float2* h0p  = hsh + (2 * tr)     * 258;
    const float2* h1p  = hsh + (2 * tr + 1) * 258;

    // h-build mapping
    const int ch   = tid & 127;
    const int half = tid >> 7;

    const size_t hb_b = (size_t)b * (HROWS + 1) * HIDC;
    int* c_own  = &g_done[(b * 4 + rg) * 8];
    int* c_prev = &g_done[(b * 4 + rg - 1) * 8];

    __syncthreads();

    for (int t = 0; t < TSTEPS; ++t) {
        // ---- prefetch Z (independent of peers) before the wait
        const int w = t - ru;
        const bool inband = (w >= 0) && (w < WCOLS);
        float zs[8];
        if (inband) {
            const float* Zp = g_Z + ((((size_t)b * HROWS + ru) * WCOLS + w) << 9) + cbase + jq;
#pragma unroll
            for (int g = 0; g < 4; ++g) {
                float2 zv = *(const float2*)(Zp + (g << 7));
                zs[g * 2 + 0] = zv.x; zs[g * 2 + 1] = zv.y;
            }
        } else {
#pragma unroll
            for (int i = 0; i < 8; ++i) zs[i] = bisr[i];
        }

        // ---- wait for producers: own rg peers (channel split) + rg-1 (row r0-1)
        if (t > 0) {
            const int need = 4 * t;
            if (tid == 0)            { while (ld_acquire_gpu(c_own)  < need) {} }
            if (tid == 32 && rg > 0) { while (ld_acquire_gpu(c_prev) < need) {} }
            __syncthreads();
        }
        const float* hin  = g_h + (size_t)(t & 1) * (BATCH * (HROWS + 1) * HIDC) + hb_b;
        float*       hout = g_h + (size_t)((t + 1) & 1) * (BATCH * (HROWS + 1) * HIDC) + hb_b;

        // ---- build duplicated h tile, transposed [m][k] (conflict-free stores)
        // slot r0+rr holds global row r0+rr-1; dk0(m)=slot r0+m, dk1(m)=slot r0+m+1
#pragma unroll
        for (int rr = half; rr < 17; rr += 2) {
            float v = hin[(r0 + rr) * HIDC + ch];
            float2 d = make_float2(v, v);
            if (rr < 16)  hsh[rr * 258 + ch] = d;            // k = ch        (dk=0)
            if (rr >= 1)  hsh[(rr - 1) * 258 + 128 + ch] = d; // k = 128 + ch (dk=1)
        }
        __syncthreads();

        // ---- micro-GEMM: hs[m][ol] = sum_k Wsh[k][ol] * h_k[m]
        ull acc0 = 0, acc1 = 0, acc2 = 0, acc3 = 0;
#pragma unroll 8
        for (int k = 0; k < 256; ++k) {
            ulonglong2 w2 = *(const ulonglong2*)(wcol + (k << 7));
            ull ha = *(const ull*)(h0p + k);
            ull hb = *(const ull*)(h1p + k);
            acc0 = fma2(ha, w2.x, acc0);  acc1 = fma2(ha, w2.y, acc1);
            acc2 = fma2(hb, w2.x, acc2);  acc3 = fma2(hb, w2.y, acc3);
        }
        {
            float2 a0 = *(float2*)&acc0, a1 = *(float2*)&acc1;
            float2 a2 = *(float2*)&acc2, a3 = *(float2*)&acc3;
            *(float4*)(zsh + (2 * tr)     * 132 + (tc << 2)) = make_float4(a0.x, a0.y, a1.x, a1.y);
            *(float4*)(zsh + (2 * tr + 1) * 132 + (tc << 2)) = make_float4(a2.x, a2.y, a3.x, a3.y);
        }
        __syncthreads();

        // ---- gates + state update (thread: row ru, channels cbase+jq, +1)
        float2 hsg[4];
#pragma unroll
        for (int g = 0; g < 4; ++g)
            hsg[g] = *(const float2*)(zsh + mu * 132 + (g << 5) + jq);

        float hvals[2];
#pragma unroll
        for (int q = 0; q < 2; ++q) {
            float zi = ((q == 0) ? hsg[0].x : hsg[0].y) + zs[0 + q] + bssr[0 + q];
            float zf = ((q == 0) ? hsg[1].x : hsg[1].y) + zs[2 + q] + bssr[2 + q];
            float zo = ((q == 0) ? hsg[2].x : hsg[2].y) + zs[4 + q] + bssr[4 + q];
            float zg = ((q == 0) ? hsg[3].x : hsg[3].y) + zs[6 + q] + bssr[6 + q];
            float ig = sigmoidf_fast(zi);
            float fg = sigmoidf_fast(zf);
            float og = sigmoidf_fast(zo);
            float gg = tanhf_fast(zg);
            float cc = fg * creg[q] + ig * gg;
            creg[q] = cc;
            hvals[q] = og * tanhf_fast(cc);
        }
        // publish h (slot ru+1), write output if in-band
        *(float2*)(hout + (ru + 1) * HIDC + cbase + jq) = make_float2(hvals[0], hvals[1]);
        if (inband) {
            size_t obase = (((size_t)b << 7) + cbase + jq) << 12;
            out[obase + (ru << 6) + w]          = hvals[0];
            out[obase + 4096 + (ru << 6) + w]   = hvals[1];
        }

        __syncthreads();                       // all h writes done block-wide
        if (tid == 0 && t + 1 < TSTEPS)
            red_release_add(c_own, 1);         // release covers the whole block's writes
    }
}

// ============================================================================
extern "C" void kernel_launch(void* const* d_in, const int* in_sizes, int n_in,
                              void* d_out, int out_size) {
    const float* x    = (const float*)d_in[0];
    const float* w_is = (const float*)d_in[1];
    const float* b_is = (const float*)d_in[2];
    const float* w_ss = (const float*)d_in[3];
    const float* b_ss = (const float*)d_in[4];
    float* out = (float*)d_out;

    cudaFuncSetAttribute(zprep_kernel, cudaFuncAttributeMaxDynamicSharedMemorySize, ZPREP_SMEM);
    cudaFuncSetAttribute(scan_kernel,  cudaFuncAttributeMaxDynamicSharedMemorySize, SCAN_SMEM);

    init_kernel<<<520, 256>>>();
    zprep_kernel<<<dim3(512, 4), 256, ZPREP_SMEM>>>(x, w_is, b_is);
    scan_kernel<<<128, 256, SCAN_SMEM>>>(w_ss, b_is, b_ss, out);
}

// round 15
// speedup vs baseline: 1.3748x; 1.3748x over previous
#include <cuda_runtime.h>
#include <cstdint>
#include <cstddef>

#define BATCH  8
#define HIDC   128
#define HROWS  64
#define WCOLS  64
#define TSTEPS 127   // 2*W - 1

typedef unsigned long long ull;

// ---------------- scratch (static device globals; no runtime allocation) ----
__device__ float g_Z[(size_t)BATCH * HROWS * WCOLS * 512]; // [b][r][w][o], includes b_is
__device__ float g_h[2 * BATCH * (HROWS + 1) * HIDC];      // [parity][b][row+1][c]; slot 0 = zero pad
__device__ int   g_done[BATCH * 8];                        // per-batch counters, stride 8 ints

// ---------------- packed f32x2 helpers -------------------------------------
__device__ __forceinline__ ull fma2(ull a, ull b, ull c) {
    ull d;
    asm("fma.rn.f32x2 %0, %1, %2, %3;" : "=l"(d) : "l"(a), "l"(b), "l"(c));
    return d;
}
__device__ __forceinline__ ull dup2(float x) {
    ull d;
    asm("mov.b64 %0, {%1, %1};" : "=l"(d) : "f"(x));
    return d;
}
__device__ __forceinline__ float sigmoidf_fast(float z) {
    return __fdividef(1.0f, 1.0f + __expf(-z));
}
__device__ __forceinline__ float tanhf_fast(float z) {
    return 1.0f - __fdividef(2.0f, __expf(2.0f * z) + 1.0f);
}
__device__ __forceinline__ int ld_acquire_gpu(const int* p) {
    int v;
    asm volatile("ld.acquire.gpu.global.s32 %0, [%1];" : "=r"(v) : "l"(p) : "memory");
    return v;
}
__device__ __forceinline__ void red_release_add(int* p, int v) {
    asm volatile("red.release.gpu.global.add.s32 [%0], %1;" :: "l"(p), "r"(v) : "memory");
}

// ============================================================================
// Kernel 0: zero h state + flags (re-run on every graph replay)
// ============================================================================
__global__ void init_kernel() {
    int i = blockIdx.x * blockDim.x + threadIdx.x;
    const int n = 2 * BATCH * (HROWS + 1) * HIDC;
    if (i < n) g_h[i] = 0.0f;
    if (i < BATCH * 8) g_done[i] = 0;
}

// ============================================================================
// Kernel 1: Z[b][r][w][o] = b_is[o] + sum_c x[b][c][r][w] * w_is[o][c]
// grid = (512 = b*64+r, 4 out-tiles of 128), 256 threads
// ============================================================================
#define ZPREP_SMEM ((8192 + 128 * 132) * 4)

__global__ void __launch_bounds__(256) zprep_kernel(
    const float* __restrict__ x, const float* __restrict__ w_is,
    const float* __restrict__ b_is)
{
    extern __shared__ float sm1[];
    float* xsh = sm1;          // [k=128][w=64]
    float* wsh = sm1 + 8192;   // [k=128][ol=128 pad 132]

    const int tid = threadIdx.x;
    const int b   = blockIdx.x >> 6;
    const int r   = blockIdx.x & 63;
    const int nt  = blockIdx.y;

#pragma unroll 8
    for (int i = 0; i < 32; ++i) {
        int idx = tid + (i << 8);
        int c = idx >> 6, w = idx & 63;
        xsh[idx] = x[(((size_t)(b << 7) + c) << 12) + (r << 6) + w];
    }
#pragma unroll 8
    for (int i = 0; i < 64; ++i) {
        int idx = tid + (i << 8);
        int ol = idx >> 7, c = idx & 127;
        wsh[c * 132 + ol] = w_is[(((nt << 7) + ol) << 7) + c];
    }
    __syncthreads();

    const int pc = (tid & 15) << 2;  // 4 w-positions
    const int oc = (tid >> 4) << 3;  // 8 outputs
    ull acc[16];
#pragma unroll
    for (int i = 0; i < 16; ++i) acc[i] = 0ull;

#pragma unroll 4
    for (int k = 0; k < 128; ++k) {
        float4 xv = *(const float4*)(xsh + (k << 6) + pc);
        ulonglong2 w0 = *(const ulonglong2*)(wsh + k * 132 + oc);
        ulonglong2 w1 = *(const ulonglong2*)(wsh + k * 132 + oc + 4);
        ull x0 = dup2(xv.x), x1 = dup2(xv.y), x2 = dup2(xv.z), x3 = dup2(xv.w);
        acc[ 0] = fma2(x0, w0.x, acc[ 0]);  acc[ 1] = fma2(x0, w0.y, acc[ 1]);
        acc[ 2] = fma2(x0, w1.x, acc[ 2]);  acc[ 3] = fma2(x0, w1.y, acc[ 3]);
        acc[ 4] = fma2(x1, w0.x, acc[ 4]);  acc[ 5] = fma2(x1, w0.y, acc[ 5]);
        acc[ 6] = fma2(x1, w1.x, acc[ 6]);  acc[ 7] = fma2(x1, w1.y, acc[ 7]);
        acc[ 8] = fma2(x2, w0.x, acc[ 8]);  acc[ 9] = fma2(x2, w0.y, acc[ 9]);
        acc[10] = fma2(x2, w1.x, acc[10]);  acc[11] = fma2(x2, w1.y, acc[11]);
        acc[12] = fma2(x3, w0.x, acc[12]);  acc[13] = fma2(x3, w0.y, acc[13]);
        acc[14] = fma2(x3, w1.x, acc[14]);  acc[15] = fma2(x3, w1.y, acc[15]);
    }

    float bo[8];
#pragma unroll
    for (int j = 0; j < 8; ++j) bo[j] = b_is[(nt << 7) + oc + j];

#pragma unroll
    for (int p = 0; p < 4; ++p) {
        float2 a0 = *(float2*)&acc[p * 4 + 0];
        float2 a1 = *(float2*)&acc[p * 4 + 1];
        float2 a2 = *(float2*)&acc[p * 4 + 2];
        float2 a3 = *(float2*)&acc[p * 4 + 3];
        float* zp = g_Z + (((size_t)blockIdx.x << 6) + pc + p) * 512 + (nt << 7) + oc;
        *(float4*)(zp)     = make_float4(a0.x + bo[0], a0.y + bo[1], a1.x + bo[2], a1.y + bo[3]);
        *(float4*)(zp + 4) = make_float4(a2.x + bo[4], a2.y + bo[5], a3.x + bo[6], a3.y + bo[7]);
    }
}

// ============================================================================
// Kernel 2: persistent diagonal scan, 256 threads, K-split register blocking.
// grid = 128 CTAs: bx = b*16 + rg*4 + cg. CTA owns rows [rg*16, rg*16+16),
// hidden channels [cg*32, cg*32+32) -> gate outputs {g*128 + cg*32 + j}.
// Warp (kg = wid>>1, rh = wid&1): tile 8 rows x 128 outs over k in
// [kg*64, kg*64+64). Cross-warp k-reduction via psh, folded into gate phase.
// Sync: GLOBAL per-batch counter (16 CTAs), need = 16t. This bounds skew
// between ANY two CTAs of a batch to < 1 step, making the 2-deep parity
// buffer provably safe (the finer per-rg scheme raced: rg-1 could overwrite
// the parity slot rg was still reading).
// ============================================================================
// Wsh  [k=256][ol=128] floats           = 131072 B
// hsh  float2 [k=256][m=16 pad 18]      =  36864 B  ((h,h) dup pairs)
// psh  [kg=4][m=16][ol=128] floats      =  32768 B
#define SCAN_SMEM (131072 + 36864 + 32768)

__global__ void __launch_bounds__(256, 1) scan_kernel(
    const float* __restrict__ w_ss, const float* __restrict__ b_is,
    const float* __restrict__ b_ss, float* __restrict__ out)
{
    extern __shared__ float sm[];
    float*  Wsh  = sm;                         // [k][ol]
    float2* hsh2 = (float2*)(sm + 32768);      // [k][m pad 18]
    float*  psh  = sm + 32768 + 9216;          // [kg][m][ol]

    const int tid  = threadIdx.x;
    const int lane = tid & 31;
    const int wid  = tid >> 5;
    const int bx   = blockIdx.x;
    const int cg   = bx & 3;
    const int rg   = (bx >> 2) & 3;
    const int b    = bx >> 4;
    const int r0   = rg << 4;
    const int cbase = cg << 5;

    // resident weights: k<128 -> (dk=0, c=k) pairs h[r-1]; k>=128 -> (dk=1, c=k-128) pairs h[r]
#pragma unroll 4
    for (int i = 0; i < 128; ++i) {
        int idx = tid + (i << 8);
        int k = idx >> 7, ol = idx & 127;
        int g = ol >> 5, j = ol & 31;
        int oglb = (g << 7) + cbase + j;
        int dk = k >> 7, c = k & 127;
        Wsh[idx] = w_ss[(oglb << 8) + (c << 1) + dk];
    }

    // update-phase mapping: row mu (16), 2 channels jq, jq+1 within cg
    const int mu = tid >> 4;
    const int jq = (tid & 15) << 1;
    const int ru = r0 + mu;

    float bisr[8], bssr[8];
#pragma unroll
    for (int g = 0; g < 4; ++g)
#pragma unroll
        for (int q = 0; q < 2; ++q) {
            int o = (g << 7) + cbase + jq + q;
            bisr[g * 2 + q] = b_is[o];
            bssr[g * 2 + q] = b_ss[o];
        }
    float creg[2] = {0.f, 0.f};

    // GEMM mapping
    const int kg = wid >> 1;      // k-group: 64 k values
    const int rh = wid & 1;       // row half: 8 rows
    const float*  wp0 = Wsh  + ((kg << 6) << 7) + (lane << 2);
    const float2* hp0 = hsh2 + (kg << 6) * 18 + (rh << 3);
    float*        pp0 = psh  + (((kg << 4) + (rh << 3)) << 7) + (lane << 2);

    // h-build mapping
    const int ch   = tid & 127;
    const int half = tid >> 7;

    const size_t hb_b = (size_t)b * (HROWS + 1) * HIDC;
    int* c_bat = &g_done[b * 8];

    __syncthreads();

    for (int t = 0; t < TSTEPS; ++t) {
        // ---- prefetch Z (independent of peers) before the wait
        const int w = t - ru;
        const bool inband = (w >= 0) && (w < WCOLS);
        float zs[8];
        if (inband) {
            const float* Zp = g_Z + ((((size_t)b * HROWS + ru) * WCOLS + w) << 9) + cbase + jq;
#pragma unroll
            for (int g = 0; g < 4; ++g) {
                float2 zv = *(const float2*)(Zp + (g << 7));
                zs[g * 2 + 0] = zv.x; zs[g * 2 + 1] = zv.y;
            }
        } else {
#pragma unroll
            for (int i = 0; i < 8; ++i) zs[i] = bisr[i];
        }

        // ---- global per-batch lockstep: wait until all 16 CTAs finished t-1
        if (t > 0) {
            if (tid == 0) {
                const int need = 16 * t;
                while (ld_acquire_gpu(c_bat) < need) {}
            }
            __syncthreads();
        }
        const float* hin  = g_h + (size_t)(t & 1) * (BATCH * (HROWS + 1) * HIDC) + hb_b;
        float*       hout = g_h + (size_t)((t + 1) & 1) * (BATCH * (HROWS + 1) * HIDC) + hb_b;

        // ---- build duplicated h tile, layout [k][m pad 18]
        // slot r0+rr holds global row r0+rr-1; dk0: k=ch, m=rr; dk1: k=128+ch, m=rr-1
#pragma unroll
        for (int rr = half; rr < 17; rr += 2) {
            float v = hin[(r0 + rr) * HIDC + ch];
            float2 d = make_float2(v, v);
            if (rr < 16) hsh2[ch * 18 + rr] = d;
            if (rr >= 1) hsh2[(128 + ch) * 18 + (rr - 1)] = d;
        }
        __syncthreads();

        // ---- micro-GEMM: warp computes partial hs over its 64-k slice
        {
            ull acc[8][2];
#pragma unroll
            for (int r = 0; r < 8; ++r) { acc[r][0] = 0ull; acc[r][1] = 0ull; }
            const float*  wp = wp0;
            const float2* hp = hp0;
#pragma unroll 4
            for (int kk = 0; kk < 64; ++kk) {
                ulonglong2 wv = *(const ulonglong2*)wp;      // w[4lane..4lane+3]
                ulonglong2 h01 = *(const ulonglong2*)(hp);
                ulonglong2 h23 = *(const ulonglong2*)(hp + 2);
                ulonglong2 h45 = *(const ulonglong2*)(hp + 4);
                ulonglong2 h67 = *(const ulonglong2*)(hp + 6);
                wp += 128; hp += 18;
                acc[0][0] = fma2(h01.x, wv.x, acc[0][0]);  acc[0][1] = fma2(h01.x, wv.y, acc[0][1]);
                acc[1][0] = fma2(h01.y, wv.x, acc[1][0]);  acc[1][1] = fma2(h01.y, wv.y, acc[1][1]);
                acc[2][0] = fma2(h23.x, wv.x, acc[2][0]);  acc[2][1] = fma2(h23.x, wv.y, acc[2][1]);
                acc[3][0] = fma2(h23.y, wv.x, acc[3][0]);  acc[3][1] = fma2(h23.y, wv.y, acc[3][1]);
                acc[4][0] = fma2(h45.x, wv.x, acc[4][0]);  acc[4][1] = fma2(h45.x, wv.y, acc[4][1]);
                acc[5][0] = fma2(h45.y, wv.x, acc[5][0]);  acc[5][1] = fma2(h45.y, wv.y, acc[5][1]);
                acc[6][0] = fma2(h67.x, wv.x, acc[6][0]);  acc[6][1] = fma2(h67.x, wv.y, acc[6][1]);
                acc[7][0] = fma2(h67.y, wv.x, acc[7][0]);  acc[7][1] = fma2(h67.y, wv.y, acc[7][1]);
            }
#pragma unroll
            for (int r = 0; r < 8; ++r) {
                float2 a0 = *(float2*)&acc[r][0];
                float2 a1 = *(float2*)&acc[r][1];
                *(float4*)(pp0 + (r << 7)) = make_float4(a0.x, a0.y, a1.x, a1.y);
            }
        }
        __syncthreads();

        // ---- gates + state update (thread: row ru, channels cbase+jq, +1)
        // reduce 4 k-group partials inline
        float hs[8];
#pragma unroll
        for (int g = 0; g < 4; ++g) {
            const int olw = (g << 5) + jq;
            float2 s0 = *(const float2*)(psh + ((0 * 16 + mu) << 7) + olw);
            float2 s1 = *(const float2*)(psh + ((1 * 16 + mu) << 7) + olw);
            float2 s2 = *(const float2*)(psh + ((2 * 16 + mu) << 7) + olw);
            float2 s3 = *(const float2*)(psh + ((3 * 16 + mu) << 7) + olw);
            hs[g * 2 + 0] = (s0.x + s1.x) + (s2.x + s3.x);
            hs[g * 2 + 1] = (s0.y + s1.y) + (s2.y + s3.y);
        }

        float hvals[2];
#pragma unroll
        for (int q = 0; q < 2; ++q) {
            float zi = hs[0 + q] + zs[0 + q] + bssr[0 + q];
            float zf = hs[2 + q] + zs[2 + q] + bssr[2 + q];
            float zo = hs[4 + q] + zs[4 + q] + bssr[4 + q];
            float zg = hs[6 + q] + zs[6 + q] + bssr[6 + q];
            float ig = sigmoidf_fast(zi);
            float fg = sigmoidf_fast(zf);
            float og = sigmoidf_fast(zo);
            float gg = tanhf_fast(zg);
            float cc = fg * creg[q] + ig * gg;
            creg[q] = cc;
            hvals[q] = og * tanhf_fast(cc);
        }
        // publish h (slot ru+1), write output if in-band
        *(float2*)(hout + (ru + 1) * HIDC + cbase + jq) = make_float2(hvals[0], hvals[1]);
        if (inband) {
            size_t obase = (((size_t)b << 7) + cbase + jq) << 12;
            out[obase + (ru << 6) + w]        = hvals[0];
            out[obase + 4096 + (ru << 6) + w] = hvals[1];
        }

        __syncthreads();                       // all h writes done block-wide
        if (tid == 0 && t + 1 < TSTEPS)
            red_release_add(c_bat, 1);         // release covers whole block's writes
    }
}

// ============================================================================
extern "C" void kernel_launch(void* const* d_in, const int* in_sizes, int n_in,
                              void* d_out, int out_size) {
    const float* x    = (const float*)d_in[0];
    const float* w_is = (const float*)d_in[1];
    const float* b_is = (const float*)d_in[2];
    const float* w_ss = (const float*)d_in[3];
    const float* b_ss = (const float*)d_in[4];
    float* out = (float*)d_out;

    cudaFuncSetAttribute(zprep_kernel, cudaFuncAttributeMaxDynamicSharedMemorySize, ZPREP_SMEM);
    cudaFuncSetAttribute(scan_kernel,  cudaFuncAttributeMaxDynamicSharedMemorySize, SCAN_SMEM);

    init_kernel<<<520, 256>>>();
    zprep_kernel<<<dim3(512, 4), 256, ZPREP_SMEM>>>(x, w_is, b_is);
    scan_kernel<<<128, 256, SCAN_SMEM>>>(w_ss, b_is, b_ss, out);
}

// round 17
// speedup vs baseline: 2.3430x; 1.7042x over previous
#include <cuda_runtime.h>
#include <cuda_bf16.h>
#include <cstdint>
#include <cstddef>

#define BATCH  8
#define HIDC   128
#define HROWS  64
#define WCOLS  64
#define TSTEPS 127   // 2*W - 1

typedef unsigned long long ull;

// ---------------- scratch (static device globals; no runtime allocation) ----
__device__ float g_Z[(size_t)BATCH * HROWS * WCOLS * 512]; // [b][r][w][o], includes b_is
__device__ float g_h[2 * BATCH * (HROWS + 1) * HIDC];      // [parity][b][row+1][c]; slot 0 = zero pad
__device__ int   g_done[BATCH * 8];                        // per-batch counters, stride 8 ints

// ---------------- helpers ---------------------------------------------------
__device__ __forceinline__ ull fma2(ull a, ull b, ull c) {
    ull d;
    asm("fma.rn.f32x2 %0, %1, %2, %3;" : "=l"(d) : "l"(a), "l"(b), "l"(c));
    return d;
}
__device__ __forceinline__ ull dup2(float x) {
    ull d;
    asm("mov.b64 %0, {%1, %1};" : "=l"(d) : "f"(x));
    return d;
}
__device__ __forceinline__ float sigmoidf_fast(float z) {
    return __fdividef(1.0f, 1.0f + __expf(-z));
}
__device__ __forceinline__ float tanhf_fast(float z) {
    return 1.0f - __fdividef(2.0f, __expf(2.0f * z) + 1.0f);
}
__device__ __forceinline__ int ld_acquire_gpu(const int* p) {
    int v;
    asm volatile("ld.acquire.gpu.global.s32 %0, [%1];" : "=r"(v) : "l"(p) : "memory");
    return v;
}
__device__ __forceinline__ void red_release_add(int* p, int v) {
    asm volatile("red.release.gpu.global.add.s32 [%0], %1;" :: "l"(p), "r"(v) : "memory");
}
// pack bf16x2: lo16 = bf16(a), hi16 = bf16(b); lo = residual pack likewise
__device__ __forceinline__ void split2(float a, float b, uint32_t& hi, uint32_t& lo) {
    uint32_t h;
    asm("cvt.rn.bf16x2.f32 %0, %1, %2;" : "=r"(h) : "f"(b), "f"(a));   // hi16=b, lo16=a
    float ra = __uint_as_float(h << 16);
    float rb = __uint_as_float(h & 0xFFFF0000u);
    float la = a - ra, lb = b - rb;
    asm("cvt.rn.bf16x2.f32 %0, %1, %2;" : "=r"(lo) : "f"(lb), "f"(la));
    hi = h;
}
// D[16m x 8n] += A[16m x 16k](bf16,row) * B[16k x 8n](bf16,col)
__device__ __forceinline__ void mma16816(float* c, const uint32_t* a, uint32_t b0, uint32_t b1) {
    asm volatile(
        "mma.sync.aligned.m16n8k16.row.col.f32.bf16.bf16.f32 "
        "{%0,%1,%2,%3}, {%4,%5,%6,%7}, {%8,%9}, {%0,%1,%2,%3};"
        : "+f"(c[0]), "+f"(c[1]), "+f"(c[2]), "+f"(c[3])
        : "r"(a[0]), "r"(a[1]), "r"(a[2]), "r"(a[3]), "r"(b0), "r"(b1));
}

// ============================================================================
// Kernel 0: zero h state + flags (re-run on every graph replay)
// ============================================================================
__global__ void init_kernel() {
    int i = blockIdx.x * blockDim.x + threadIdx.x;
    const int n = 2 * BATCH * (HROWS + 1) * HIDC;
    if (i < n) g_h[i] = 0.0f;
    if (i < BATCH * 8) g_done[i] = 0;
}

// ============================================================================
// Kernel 1: Z[b][r][w][o] = b_is[o] + sum_c x[b][c][r][w] * w_is[o][c]
// ============================================================================
#define ZPREP_SMEM ((8192 + 128 * 132) * 4)

__global__ void __launch_bounds__(256) zprep_kernel(
    const float* __restrict__ x, const float* __restrict__ w_is,
    const float* __restrict__ b_is)
{
    extern __shared__ float sm1[];
    float* xsh = sm1;          // [k=128][w=64]
    float* wsh = sm1 + 8192;   // [k=128][ol=128 pad 132]

    const int tid = threadIdx.x;
    const int b   = blockIdx.x >> 6;
    const int r   = blockIdx.x & 63;
    const int nt  = blockIdx.y;

#pragma unroll 8
    for (int i = 0; i < 32; ++i) {
        int idx = tid + (i << 8);
        int c = idx >> 6, w = idx & 63;
        xsh[idx] = x[(((size_t)(b << 7) + c) << 12) + (r << 6) + w];
    }
#pragma unroll 8
    for (int i = 0; i < 64; ++i) {
        int idx = tid + (i << 8);
        int ol = idx >> 7, c = idx & 127;
        wsh[c * 132 + ol] = w_is[(((nt << 7) + ol) << 7) + c];
    }
    __syncthreads();

    const int pc = (tid & 15) << 2;
    const int oc = (tid >> 4) << 3;
    ull acc[16];
#pragma unroll
    for (int i = 0; i < 16; ++i) acc[i] = 0ull;

#pragma unroll 4
    for (int k = 0; k < 128; ++k) {
        float4 xv = *(const float4*)(xsh + (k << 6) + pc);
        ulonglong2 w0 = *(const ulonglong2*)(wsh + k * 132 + oc);
        ulonglong2 w1 = *(const ulonglong2*)(wsh + k * 132 + oc + 4);
        ull x0 = dup2(xv.x), x1 = dup2(xv.y), x2 = dup2(xv.z), x3 = dup2(xv.w);
        acc[ 0] = fma2(x0, w0.x, acc[ 0]);  acc[ 1] = fma2(x0, w0.y, acc[ 1]);
        acc[ 2] = fma2(x0, w1.x, acc[ 2]);  acc[ 3] = fma2(x0, w1.y, acc[ 3]);
        acc[ 4] = fma2(x1, w0.x, acc[ 4]);  acc[ 5] = fma2(x1, w0.y, acc[ 5]);
        acc[ 6] = fma2(x1, w1.x, acc[ 6]);  acc[ 7] = fma2(x1, w1.y, acc[ 7]);
        acc[ 8] = fma2(x2, w0.x, acc[ 8]);  acc[ 9] = fma2(x2, w0.y, acc[ 9]);
        acc[10] = fma2(x2, w1.x, acc[10]);  acc[11] = fma2(x2, w1.y, acc[11]);
        acc[12] = fma2(x3, w0.x, acc[12]);  acc[13] = fma2(x3, w0.y, acc[13]);
        acc[14] = fma2(x3, w1.x, acc[14]);  acc[15] = fma2(x3, w1.y, acc[15]);
    }

    float bo[8];
#pragma unroll
    for (int j = 0; j < 8; ++j) bo[j] = b_is[(nt << 7) + oc + j];

#pragma unroll
    for (int p = 0; p < 4; ++p) {
        float2 a0 = *(float2*)&acc[p * 4 + 0];
        float2 a1 = *(float2*)&acc[p * 4 + 1];
        float2 a2 = *(float2*)&acc[p * 4 + 2];
        float2 a3 = *(float2*)&acc[p * 4 + 3];
        float* zp = g_Z + (((size_t)blockIdx.x << 6) + pc + p) * 512 + (nt << 7) + oc;
        *(float4*)(zp)     = make_float4(a0.x + bo[0], a0.y + bo[1], a1.x + bo[2], a1.y + bo[3]);
        *(float4*)(zp + 4) = make_float4(a2.x + bo[4], a2.y + bo[5], a3.x + bo[6], a3.y + bo[7]);
    }
}

// ============================================================================
// Kernel 2: persistent diagonal scan via mma.sync bf16 split precision.
// grid = 128 CTAs (b*16 + rg*4 + cg), 256 threads (8 warps).
// Per step per CTA: D[o=128][m=16] = W^T * h, K=256 via m16n8k16 HMMA,
// 3 passes (W1*h1 + W1*h2 + W2*h1), FP32 fragment accumulation.
// W (split hi/lo) resident in REGISTERS per warp (warp owns 16 outputs).
// h tile rebuilt per step as [n=16][k=256] bf16 hi/lo in SMEM (row pad 264).
// k ordering = w_ss natural: k = 2c + dk; B[n][2c+dk] = hin[(r0+n+dk)*128+c].
// Sync: global per-batch counter (16 CTAs), need = 16t (parity-safe).
// ============================================================================
#define OFF_HI   0
#define OFF_LO   8448
#define OFF_ZSH  16896
#define SCAN_SMEM (16896 + 16 * 132 * 4)   // 25344 B
#define HROWSTRIDE 132                      // words per h row (264 bf16)

__global__ void __launch_bounds__(256, 1) scan_kernel(
    const float* __restrict__ w_ss, const float* __restrict__ b_is,
    const float* __restrict__ b_ss, float* __restrict__ out)
{
    extern __shared__ char smem[];
    uint32_t* Hh = (uint32_t*)(smem + OFF_HI);   // [n=16][k/2=128 pad 132]
    uint32_t* Hl = (uint32_t*)(smem + OFF_LO);
    float*    zsh = (float*)(smem + OFF_ZSH);    // [m=16][ol=128 pad 132]

    const int tid  = threadIdx.x;
    const int lane = tid & 31;
    const int wid  = tid >> 5;
    const int bx   = blockIdx.x;
    const int cg   = bx & 3;
    const int rg   = (bx >> 2) & 3;
    const int b    = bx >> 4;
    const int r0   = rg << 4;
    const int cbase = cg << 5;

    // ---- load W into registers (split hi/lo), once --------------------------
    // warp owns local outputs [wid*16, wid*16+16); lane: g=lane>>2, tc=lane&3
    const int g  = lane >> 2;
    const int tc = lane & 3;
    uint32_t A1[16][4], A2[16][4];
    {
        const int o1 = (wid << 4) + g;
        const int o2 = o1 + 8;
        const int og1 = ((o1 >> 5) << 7) + cbase + (o1 & 31);
        const int og2 = ((o2 >> 5) << 7) + cbase + (o2 & 31);
        const float* w1p = w_ss + ((size_t)og1 << 8);
        const float* w2p = w_ss + ((size_t)og2 << 8);
#pragma unroll
        for (int kt = 0; kt < 16; ++kt) {
            int kb = (kt << 4) + (tc << 1);
            float2 f0 = *(const float2*)(w1p + kb);
            float2 f1 = *(const float2*)(w2p + kb);
            float2 f2 = *(const float2*)(w1p + kb + 8);
            float2 f3 = *(const float2*)(w2p + kb + 8);
            split2(f0.x, f0.y, A1[kt][0], A2[kt][0]);
            split2(f1.x, f1.y, A1[kt][1], A2[kt][1]);
            split2(f2.x, f2.y, A1[kt][2], A2[kt][2]);
            split2(f3.x, f3.y, A1[kt][3], A2[kt][3]);
        }
    }

    // ---- gate-phase mapping: row mu, channels jq, jq+1 ----------------------
    const int mu = tid >> 4;
    const int jq = (tid & 15) << 1;
    const int ru = r0 + mu;
    float bisr[8], bssr[8];
#pragma unroll
    for (int gg = 0; gg < 4; ++gg)
#pragma unroll
        for (int q = 0; q < 2; ++q) {
            int o = (gg << 7) + cbase + jq + q;
            bisr[gg * 2 + q] = b_is[o];
            bssr[gg * 2 + q] = b_ss[o];
        }
    float creg[2] = {0.f, 0.f};

    // ---- h-build mapping: n = tid>>4 (row), chunk = tid&15 (16 k = 8 chans)
    const int hn = tid >> 4;
    const int hc = tid & 15;
    const uint32_t hrow_b = (uint32_t)(hn * (HROWSTRIDE * 4) + (hc << 5)); // bytes

    // B-fragment word offsets (per warp lane): rows g (ntile0), 8+g (ntile1)
    const int rw0 = g * HROWSTRIDE + tc;
    const int rw1 = (8 + g) * HROWSTRIDE + tc;

    // D-store pointers: rows tc*2(+1) per ntile, cols o1/o2
    const int o1 = (wid << 4) + g;
    const int o2 = o1 + 8;

    const size_t hb_b = (size_t)b * (HROWS + 1) * HIDC;
    int* c_bat = &g_done[b * 8];

    __syncthreads();

    for (int t = 0; t < TSTEPS; ++t) {
        // ---- prefetch Z before the wait (independent of peers)
        const int w = t - ru;
        const bool inband = (w >= 0) && (w < WCOLS);
        float zs[8];
        if (inband) {
            const float* Zp = g_Z + ((((size_t)b * HROWS + ru) * WCOLS + w) << 9) + cbase + jq;
#pragma unroll
            for (int gg = 0; gg < 4; ++gg) {
                float2 zv = *(const float2*)(Zp + (gg << 7));
                zs[gg * 2 + 0] = zv.x; zs[gg * 2 + 1] = zv.y;
            }
        } else {
#pragma unroll
            for (int i = 0; i < 8; ++i) zs[i] = bisr[i];
        }

        // ---- global per-batch lockstep (parity-safe 2-deep h buffer)
        if (t > 0) {
            if (tid == 0) {
                const int need = 16 * t;
                while (ld_acquire_gpu(c_bat) < need) {}
            }
            __syncthreads();
        }
        const float* hin  = g_h + (size_t)(t & 1) * (BATCH * (HROWS + 1) * HIDC) + hb_b;
        float*       hout = g_h + (size_t)((t + 1) & 1) * (BATCH * (HROWS + 1) * HIDC) + hb_b;

        // ---- build h tile: B[n][2c+dk] = hin[(r0+n+dk)*128 + c], split hi/lo
        {
            const float* pa = hin + (r0 + hn) * HIDC + (hc << 3);
            float4 a0 = *(const float4*)(pa);
            float4 a1 = *(const float4*)(pa + 4);
            float4 b0 = *(const float4*)(pa + HIDC);
            float4 b1 = *(const float4*)(pa + HIDC + 4);
            uint32_t hi[8], lo[8];
            split2(a0.x, b0.x, hi[0], lo[0]);
            split2(a0.y, b0.y, hi[1], lo[1]);
            split2(a0.z, b0.z, hi[2], lo[2]);
            split2(a0.w, b0.w, hi[3], lo[3]);
            split2(a1.x, b1.x, hi[4], lo[4]);
            split2(a1.y, b1.y, hi[5], lo[5]);
            split2(a1.z, b1.z, hi[6], lo[6]);
            split2(a1.w, b1.w, hi[7], lo[7]);
            *(uint4*)((char*)Hh + hrow_b)      = make_uint4(hi[0], hi[1], hi[2], hi[3]);
            *(uint4*)((char*)Hh + hrow_b + 16) = make_uint4(hi[4], hi[5], hi[6], hi[7]);
            *(uint4*)((char*)Hl + hrow_b)      = make_uint4(lo[0], lo[1], lo[2], lo[3]);
            *(uint4*)((char*)Hl + hrow_b + 16) = make_uint4(lo[4], lo[5], lo[6], lo[7]);
        }
        __syncthreads();

        // ---- HMMA: 16 k-tiles x (2 ntiles x 3 passes), fp32 accum
        float acc0[4] = {0.f, 0.f, 0.f, 0.f};
        float acc1[4] = {0.f, 0.f, 0.f, 0.f};
#pragma unroll
        for (int kt = 0; kt < 16; ++kt) {
            const int kb = kt << 3;
            uint32_t h1n0a = Hh[rw0 + kb],     h1n0b = Hh[rw0 + kb + 4];
            uint32_t h1n1a = Hh[rw1 + kb],     h1n1b = Hh[rw1 + kb + 4];
            uint32_t h2n0a = Hl[rw0 + kb],     h2n0b = Hl[rw0 + kb + 4];
            uint32_t h2n1a = Hl[rw1 + kb],     h2n1b = Hl[rw1 + kb + 4];
            mma16816(acc0, A1[kt], h1n0a, h1n0b);
            mma16816(acc1, A1[kt], h1n1a, h1n1b);
            mma16816(acc0, A1[kt], h2n0a, h2n0b);
            mma16816(acc1, A1[kt], h2n1a, h2n1b);
            mma16816(acc0, A2[kt], h1n0a, h1n0b);
            mma16816(acc1, A2[kt], h1n1a, h1n1b);
        }
        // stage D -> zsh[m][ol]: lane owns rows tc*2(+1) x outs o1,o2 per ntile
        {
            const int rA = tc << 1;
            zsh[(rA)     * HROWSTRIDE + o1] = acc0[0];
            zsh[(rA + 1) * HROWSTRIDE + o1] = acc0[1];
            zsh[(rA)     * HROWSTRIDE + o2] = acc0[2];
            zsh[(rA + 1) * HROWSTRIDE + o2] = acc0[3];
            zsh[(rA + 8) * HROWSTRIDE + o1] = acc1[0];
            zsh[(rA + 9) * HROWSTRIDE + o1] = acc1[1];
            zsh[(rA + 8) * HROWSTRIDE + o2] = acc1[2];
            zsh[(rA + 9) * HROWSTRIDE + o2] = acc1[3];
        }
        __syncthreads();

        // ---- gates + state update (thread: row ru, channels cbase+jq, +1)
        float hs[8];
#pragma unroll
        for (int gg = 0; gg < 4; ++gg) {
            float2 v = *(const float2*)(zsh + mu * HROWSTRIDE + (gg << 5) + jq);
            hs[gg * 2 + 0] = v.x; hs[gg * 2 + 1] = v.y;
        }
        float hvals[2];
#pragma unroll
        for (int q = 0; q < 2; ++q) {
            float zi = hs[0 + q] + zs[0 + q] + bssr[0 + q];
            float zf = hs[2 + q] + zs[2 + q] + bssr[2 + q];
            float zo = hs[4 + q] + zs[4 + q] + bssr[4 + q];
            float zg = hs[6 + q] + zs[6 + q] + bssr[6 + q];
            float ig = sigmoidf_fast(zi);
            float fg = sigmoidf_fast(zf);
            float og = sigmoidf_fast(zo);
            float gg2 = tanhf_fast(zg);
            float cc = fg * creg[q] + ig * gg2;
            creg[q] = cc;
            hvals[q] = og * tanhf_fast(cc);
        }
        *(float2*)(hout + (ru + 1) * HIDC + cbase + jq) = make_float2(hvals[0], hvals[1]);
        if (inband) {
            size_t obase = (((size_t)b << 7) + cbase + jq) << 12;
            out[obase + (ru << 6) + w]        = hvals[0];
            out[obase + 4096 + (ru << 6) + w] = hvals[1];
        }

        __syncthreads();                    // all h writes done block-wide
        if (tid == 0 && t + 1 < TSTEPS)
            red_release_add(c_bat, 1);      // release covers whole block's writes
    }
}

// ============================================================================
extern "C" void kernel_launch(void* const* d_in, const int* in_sizes, int n_in,
                              void* d_out, int out_size) {
    const float* x    = (const float*)d_in[0];
    const float* w_is = (const float*)d_in[1];
    const float* b_is = (const float*)d_in[2];
    const float* w_ss = (const float*)d_in[3];
    const float* b_ss = (const float*)d_in[4];
    float* out = (float*)d_out;

    cudaFuncSetAttribute(zprep_kernel, cudaFuncAttributeMaxDynamicSharedMemorySize, ZPREP_SMEM);
    cudaFuncSetAttribute(scan_kernel,  cudaFuncAttributeMaxDynamicSharedMemorySize, SCAN_SMEM);

    init_kernel<<<520, 256>>>();
    zprep_kernel<<<dim3(512, 4), 256, ZPREP_SMEM>>>(x, w_is, b_is);
    scan_kernel<<<128, 256, SCAN_SMEM>>>(w_ss, b_is, b_ss, out);
}